// round 1
// baseline (speedup 1.0000x reference)
#include <cuda_runtime.h>
#include <cuda_bf16.h>
#include <cstdint>
#include <cmath>

// ---------------------------------------------------------------------------
// GPT-OSS attention block: QKV proj -> YaRN RoPE -> sliding-window attention
// with sink -> O proj.  T=1536, HIDDEN=2880, 64 Q heads / 8 KV heads, D=64,
// window=128.  Round 0: straight fp32 baseline (tiled SGEMM + warp attention).
// ---------------------------------------------------------------------------

#define T_LEN      1536
#define HIDDEN     2880
#define N_HEADS    64
#define N_KV       8
#define HEAD_DIM   64
#define WINDOW     128
#define Q_SIZE     (N_HEADS * HEAD_DIM)          // 4096
#define KV_SIZE    (N_KV * HEAD_DIM)             // 512
#define QKV_COLS   (Q_SIZE + 2 * KV_SIZE)        // 5120
#define ATT_SCALE  0.125f                        // 1/sqrt(64)

// Scratch (no allocations allowed -> device globals)
__device__ float g_qkv[(size_t)T_LEN * QKV_COLS];    // 31.5 MB
__device__ float g_attn[(size_t)T_LEN * Q_SIZE];     // 25.2 MB

// ---------------------------------------------------------------------------
// Tiled SGEMM: C[M,N] = A[M,K] @ B[K,N] + bias[N]
// BM=BN=128, BK=16, 256 threads, 8x8 per-thread micro-tile.
// ---------------------------------------------------------------------------
__global__ __launch_bounds__(256)
void sgemm_bias_kernel(const float* __restrict__ A,
                       const float* __restrict__ B,
                       const float* __restrict__ bias,
                       float* __restrict__ C,
                       int M, int N, int K)
{
    constexpr int BM = 128, BN = 128, BK = 16, TM = 8, TN = 8;
    __shared__ float As[BK][BM];   // A stored transposed
    __shared__ float Bs[BK][BN];

    const int tid  = threadIdx.x;
    const int tcol = tid % (BN / TN);   // 0..15
    const int trow = tid / (BN / TN);   // 0..15
    const int row0 = blockIdx.y * BM;
    const int col0 = blockIdx.x * BN;

    // A loader: 4 float4 per 16-float row; 256 threads cover 64 rows/pass
    const int a_row = tid / (BK / 4);          // 0..63
    const int a_col = (tid % (BK / 4)) * 4;    // 0,4,8,12
    // B loader: 32 float4 per 128-float row; 256 threads cover 8 rows/pass
    const int b_row = tid / (BN / 4);          // 0..7
    const int b_col = (tid % (BN / 4)) * 4;

    float acc[TM][TN];
    #pragma unroll
    for (int i = 0; i < TM; i++)
        #pragma unroll
        for (int j = 0; j < TN; j++) acc[i][j] = 0.0f;

    for (int k0 = 0; k0 < K; k0 += BK) {
        // ---- load A tile (transposed into smem) ----
        #pragma unroll
        for (int p = 0; p < BM; p += 64) {
            int r  = a_row + p;
            int gr = row0 + r;
            float4 v = make_float4(0.f, 0.f, 0.f, 0.f);
            if (gr < M)
                v = *reinterpret_cast<const float4*>(A + (size_t)gr * K + (k0 + a_col));
            As[a_col + 0][r] = v.x;
            As[a_col + 1][r] = v.y;
            As[a_col + 2][r] = v.z;
            As[a_col + 3][r] = v.w;
        }
        // ---- load B tile ----
        #pragma unroll
        for (int p = 0; p < BK; p += 8) {
            int r  = b_row + p;
            int gc = col0 + b_col;
            float4 v = make_float4(0.f, 0.f, 0.f, 0.f);
            if (gc < N)
                v = *reinterpret_cast<const float4*>(B + (size_t)(k0 + r) * N + gc);
            *reinterpret_cast<float4*>(&Bs[r][b_col]) = v;
        }
        __syncthreads();

        // ---- compute ----
        #pragma unroll
        for (int kk = 0; kk < BK; kk++) {
            float4 a0 = *reinterpret_cast<const float4*>(&As[kk][trow * TM]);
            float4 a1 = *reinterpret_cast<const float4*>(&As[kk][trow * TM + 4]);
            float4 b0 = *reinterpret_cast<const float4*>(&Bs[kk][tcol * TN]);
            float4 b1 = *reinterpret_cast<const float4*>(&Bs[kk][tcol * TN + 4]);
            float af[TM] = {a0.x, a0.y, a0.z, a0.w, a1.x, a1.y, a1.z, a1.w};
            float bf[TN] = {b0.x, b0.y, b0.z, b0.w, b1.x, b1.y, b1.z, b1.w};
            #pragma unroll
            for (int i = 0; i < TM; i++)
                #pragma unroll
                for (int j = 0; j < TN; j++)
                    acc[i][j] += af[i] * bf[j];
        }
        __syncthreads();
    }

    // ---- epilogue: +bias, store ----
    #pragma unroll
    for (int i = 0; i < TM; i++) {
        int gr = row0 + trow * TM + i;
        if (gr >= M) continue;
        #pragma unroll
        for (int j = 0; j < TN; j += 4) {
            int gc = col0 + tcol * TN + j;
            if (gc < N) {  // N % 4 == 0, so full float4 in-bounds
                float4 o;
                o.x = acc[i][j + 0] + bias[gc + 0];
                o.y = acc[i][j + 1] + bias[gc + 1];
                o.z = acc[i][j + 2] + bias[gc + 2];
                o.w = acc[i][j + 3] + bias[gc + 3];
                *reinterpret_cast<float4*>(C + (size_t)gr * N + gc) = o;
            }
        }
    }
}

// ---------------------------------------------------------------------------
// YaRN RoPE, applied in-place to Q (heads 0..63) and K (heads 64..71) of g_qkv.
// One thread per (t, head, d<32) rotation pair.
// ---------------------------------------------------------------------------
__global__ void rope_kernel(const int* __restrict__ positions,
                            float* __restrict__ qkv)
{
    const int idx = blockIdx.x * blockDim.x + threadIdx.x;
    const int total = T_LEN * (N_HEADS + N_KV) * 32;
    if (idx >= total) return;

    const int d    = idx & 31;
    const int head = (idx >> 5) % (N_HEADS + N_KV);
    const int t    = idx / (32 * (N_HEADS + N_KV));

    const float p = (float)positions[t];

    const float lnB   = logf(150000.0f);
    const float freq  = expf(lnB * ((float)d / 32.0f));          // BASE^(d/half)
    const float conc  = 0.1f * logf(32.0f) + 1.0f;               // concentration
    const float twoPi = 6.283185307179586f;
    const float low   = 32.0f * logf(4096.0f / (32.0f * twoPi)) / lnB;
    const float high  = 32.0f * logf(4096.0f / (1.0f  * twoPi)) / lnB;
    float ramp = ((float)d - low) / (high - low);
    ramp = fminf(fmaxf(ramp, 0.0f), 1.0f);
    const float inv_freq = ramp / (32.0f * freq) + (1.0f - ramp) / freq;

    const float ang = p * inv_freq;
    const float c = cosf(ang) * conc;
    const float s = sinf(ang) * conc;

    // q heads occupy cols [0,4096), k heads 64..71 occupy [4096,4608): both = head*64
    float* base = qkv + (size_t)t * QKV_COLS + head * HEAD_DIM;
    const float x1 = base[d];
    const float x2 = base[d + 32];
    base[d]      = x1 * c - x2 * s;
    base[d + 32] = x2 * c + x1 * s;
}

// ---------------------------------------------------------------------------
// Sliding-window attention with sink.  One warp per (query i, head h).
// Block = 4 warps covering 4 consecutive heads of one query (same KV head ->
// strong L1 reuse of K/V rows).
// ---------------------------------------------------------------------------
__global__ __launch_bounds__(128)
void attn_kernel(const float* __restrict__ qkv,
                 const float* __restrict__ sinks,
                 float* __restrict__ out)
{
    __shared__ float p_s[4][WINDOW];
    __shared__ float q_s[4][HEAD_DIM];

    const int warp = threadIdx.x >> 5;
    const int lane = threadIdx.x & 31;
    const int i = blockIdx.x / (N_HEADS / 4);                 // query index
    const int h = (blockIdx.x % (N_HEADS / 4)) * 4 + warp;    // head index
    const int kv = h >> 3;

    // stage q into shared
    const float* qp = qkv + (size_t)i * QKV_COLS + h * HEAD_DIM;
    q_s[warp][lane]      = qp[lane];
    q_s[warp][lane + 32] = qp[lane + 32];
    __syncwarp();

    // ---- phase 1: scores ----
    const float4* q4 = reinterpret_cast<const float4*>(&q_s[warp][0]);
    float sc[4];
    float mloc = -3.0e38f;
    #pragma unroll
    for (int jj = 0; jj < 4; jj++) {
        const int slot = jj * 32 + lane;
        const int j = i - slot;
        float v = -3.0e38f;
        if (j >= 0) {
            const float4* k4 = reinterpret_cast<const float4*>(
                qkv + (size_t)j * QKV_COLS + Q_SIZE + kv * HEAD_DIM);
            float acc = 0.0f;
            #pragma unroll
            for (int dd = 0; dd < HEAD_DIM / 4; dd++) {
                float4 qv = q4[dd];
                float4 kvv = k4[dd];
                acc += qv.x * kvv.x + qv.y * kvv.y + qv.z * kvv.z + qv.w * kvv.w;
            }
            v = acc * ATT_SCALE;
        }
        sc[jj] = v;
        mloc = fmaxf(mloc, v);
    }
    #pragma unroll
    for (int off = 16; off > 0; off >>= 1)
        mloc = fmaxf(mloc, __shfl_xor_sync(0xFFFFFFFFu, mloc, off));

    const float snk = sinks[h];
    const float m = fmaxf(mloc, snk);

    float dloc = 0.0f;
    #pragma unroll
    for (int jj = 0; jj < 4; jj++) {
        float e = expf(sc[jj] - m);     // -3e38 - m underflows to exp -> 0
        p_s[warp][jj * 32 + lane] = e;
        dloc += e;
    }
    #pragma unroll
    for (int off = 16; off > 0; off >>= 1)
        dloc += __shfl_xor_sync(0xFFFFFFFFu, dloc, off);
    const float inv_denom = 1.0f / (dloc + expf(snk - m));
    __syncwarp();

    // ---- phase 2: P @ V (lanes own dims d=lane, lane+32) ----
    float acc0 = 0.0f, acc1 = 0.0f;
    const int nslots = (i + 1 < WINDOW) ? (i + 1) : WINDOW;
    for (int slot = 0; slot < nslots; slot++) {
        const int j = i - slot;
        const float* vj = qkv + (size_t)j * QKV_COLS + Q_SIZE + KV_SIZE + kv * HEAD_DIM;
        const float pj = p_s[warp][slot];
        acc0 += pj * vj[lane];
        acc1 += pj * vj[lane + 32];
    }
    float* op = out + (size_t)i * Q_SIZE + h * HEAD_DIM;
    op[lane]      = acc0 * inv_denom;
    op[lane + 32] = acc1 * inv_denom;
}

// ---------------------------------------------------------------------------
// Launch
// ---------------------------------------------------------------------------
extern "C" void kernel_launch(void* const* d_in, const int* in_sizes, int n_in,
                              void* d_out, int out_size)
{
    const int*   positions = (const int*)  d_in[0];
    const float* hidden    = (const float*)d_in[1];
    const float* W_qkv     = (const float*)d_in[2];
    const float* b_qkv     = (const float*)d_in[3];
    const float* W_o       = (const float*)d_in[4];
    const float* b_o       = (const float*)d_in[5];
    const float* sinks     = (const float*)d_in[6];
    float* out = (float*)d_out;

    float* qkv;  cudaGetSymbolAddress((void**)&qkv,  g_qkv);
    float* attn; cudaGetSymbolAddress((void**)&attn, g_attn);

    // 1) QKV projection: [1536,2880] @ [2880,5120] + b
    {
        dim3 grid(QKV_COLS / 128, T_LEN / 128);
        sgemm_bias_kernel<<<grid, 256>>>(hidden, W_qkv, b_qkv, qkv,
                                         T_LEN, QKV_COLS, HIDDEN);
    }
    // 2) RoPE in place on Q + K
    {
        const int total = T_LEN * (N_HEADS + N_KV) * 32;
        rope_kernel<<<(total + 255) / 256, 256>>>(positions, qkv);
    }
    // 3) Sliding-window attention with sink
    {
        attn_kernel<<<T_LEN * (N_HEADS / 4), 128>>>(qkv, sinks, attn);
    }
    // 4) Output projection: [1536,4096] @ [4096,2880] + b
    {
        dim3 grid((HIDDEN + 127) / 128, T_LEN / 128);
        sgemm_bias_kernel<<<grid, 256>>>(attn, W_o, b_o, out,
                                         T_LEN, HIDDEN, Q_SIZE);
    }
}

// round 3
// speedup vs baseline: 2.4483x; 2.4483x over previous
#include <cuda_runtime.h>
#include <cuda_fp16.h>
#include <cstdint>
#include <cmath>

// ---------------------------------------------------------------------------
// GPT-OSS attention block on sm_100 (plain target: no tcgen05 -> mma.sync).
// Round 3: fp16 HMMA 3-pass GEMMs + smem-blocked attention.
// ---------------------------------------------------------------------------

#define T_LEN      1536
#define HIDDEN     2880
#define N_HEADS    64
#define N_KV       8
#define HEAD_DIM   64
#define WINDOW     128
#define Q_SIZE     4096
#define KV_SIZE    512
#define QKV_COLS   5120
#define O_NPAD     2944
#define ATT_SCALE  0.125f

// ---------------- scratch ---------------------------------------------------
__device__ __align__(256) float  g_qkv   [(size_t)T_LEN * QKV_COLS];
__device__ __align__(256) __half g_h_hi  [(size_t)T_LEN * HIDDEN];
__device__ __align__(256) __half g_h_lo  [(size_t)T_LEN * HIDDEN];
__device__ __align__(256) __half g_wq_hi [(size_t)QKV_COLS * HIDDEN];   // [N,K]
__device__ __align__(256) __half g_wq_lo [(size_t)QKV_COLS * HIDDEN];
__device__ __align__(256) __half g_wo_hi [(size_t)O_NPAD * Q_SIZE];     // [N,K]
__device__ __align__(256) __half g_wo_lo [(size_t)O_NPAD * Q_SIZE];
__device__ __align__(256) __half g_a_hi  [(size_t)T_LEN * Q_SIZE];
__device__ __align__(256) __half g_a_lo  [(size_t)T_LEN * Q_SIZE];

// ---------------- helpers ---------------------------------------------------
static __device__ __forceinline__ uint32_t smem_u32(const void* p) {
    uint32_t a;
    asm("{ .reg .u64 t; cvta.to.shared.u64 t, %1; cvt.u32.u64 %0, t; }"
        : "=r"(a) : "l"(p));
    return a;
}

#define CP_ASYNC16(dst, src) \
    asm volatile("cp.async.cg.shared.global [%0], [%1], 16;" :: "r"(dst), "l"(src))
#define CP_COMMIT() asm volatile("cp.async.commit_group;")
#define CP_WAIT1()  asm volatile("cp.async.wait_group 1;")

static __device__ __forceinline__ void ldsm4(uint32_t* r, uint32_t addr) {
    asm volatile("ldmatrix.sync.aligned.m8n8.x4.shared.b16 {%0,%1,%2,%3}, [%4];"
                 : "=r"(r[0]), "=r"(r[1]), "=r"(r[2]), "=r"(r[3]) : "r"(addr));
}

static __device__ __forceinline__ void mma16816(float* d, const uint32_t* a,
                                                uint32_t b0, uint32_t b1) {
    asm volatile("mma.sync.aligned.m16n8k16.row.col.f32.f16.f16.f32 "
                 "{%0,%1,%2,%3}, {%4,%5,%6,%7}, {%8,%9}, {%0,%1,%2,%3};"
                 : "+f"(d[0]), "+f"(d[1]), "+f"(d[2]), "+f"(d[3])
                 : "r"(a[0]), "r"(a[1]), "r"(a[2]), "r"(a[3]), "r"(b0), "r"(b1));
}

// ---------------------------------------------------------------------------
// fp16 HMMA GEMM, 3-pass hi/lo:  C[M,Nreal] = A[M,K] @ B[Npad,K]^T + bias
// CTA 128x128, K-chunk 64, 3-stage cp.async, 256 threads (8 warps of 64x32).
// SW128 swizzle on 128B rows.
// ---------------------------------------------------------------------------
#define GS           3
#define STAGE_BYTES  32768       // 16KB A + 16KB B
#define GEMM_DSMEM   (GS * STAGE_BYTES + 1024)

static __device__ __forceinline__ void load_tiles256(
    uint32_t aB, uint32_t bB,
    const __half* __restrict__ Ag, const __half* __restrict__ Bg,
    int m0, int n0, int kk, int K, int tid)
{
    #pragma unroll
    for (int i = 0; i < 4; i++) {
        int chunk = tid + (i << 8);          // 0..1023
        int rw    = chunk >> 3;              // row 0..127
        int c16   = chunk & 7;               // 16B chunk in row
        uint32_t off = (uint32_t)(rw << 7) + (uint32_t)(c16 << 4);
        uint32_t sw  = off ^ ((off >> 3) & 0x70);
        const char* sa = (const char*)(Ag + (size_t)(m0 + rw) * K + kk) + (c16 << 4);
        const char* sb = (const char*)(Bg + (size_t)(n0 + rw) * K + kk) + (c16 << 4);
        CP_ASYNC16(aB + sw, sa);
        CP_ASYNC16(bB + sw, sb);
    }
}

__global__ __launch_bounds__(256)
void hgemm3_kernel(const __half* __restrict__ A_hi, const __half* __restrict__ A_lo,
                   const __half* __restrict__ B_hi, const __half* __restrict__ B_lo,
                   const float* __restrict__ bias, float* __restrict__ C,
                   int Nreal, int K)
{
    extern __shared__ char dynsmem[];
    const uint32_t tile0 = (smem_u32(dynsmem) + 1023u) & ~1023u;

    const int tid  = threadIdx.x;
    const int wid  = tid >> 5;
    const int lane = tid & 31;
    const int m0   = blockIdx.y * 128;
    const int n0   = blockIdx.x * 128;
    const int wm   = (wid & 1) * 64;
    const int wn   = (wid >> 1) * 32;

    const int r7 = lane & 7;
    const int q  = lane >> 3;
    const int rA = ((q & 1) << 3) + r7;   // row-in-16 for ldmatrix lane
    const int cq = q >> 1;                // k8-half selector

    const __half* Aps[3] = {A_hi, A_hi, A_lo};
    const __half* Bps[3] = {B_hi, B_lo, B_hi};
    const int cpp = K >> 6;
    const int nch = 3 * cpp;

    float acc[4][4][4];
    #pragma unroll
    for (int a = 0; a < 4; a++)
        #pragma unroll
        for (int b = 0; b < 4; b++)
            #pragma unroll
            for (int c = 0; c < 4; c++) acc[a][b][c] = 0.0f;

    // prologue: chunks 0..GS-2
    #pragma unroll
    for (int c = 0; c < GS - 1; c++) {
        uint32_t aB = tile0 + c * STAGE_BYTES;
        load_tiles256(aB, aB + 16384, Aps[0], Bps[0], m0, n0, c << 6, K, tid);
        CP_COMMIT();
    }

    for (int c = 0; c < nch; c++) {
        CP_WAIT1();
        __syncthreads();

        const int cn = c + GS - 1;
        if (cn < nch) {
            const int pass = cn / cpp;
            const int kk   = (cn - pass * cpp) << 6;
            uint32_t aB = tile0 + (cn % GS) * STAGE_BYTES;
            load_tiles256(aB, aB + 16384, Aps[pass], Bps[pass], m0, n0, kk, K, tid);
            CP_COMMIT();
        }

        const uint32_t aB = tile0 + (c % GS) * STAGE_BYTES;
        const uint32_t bB = aB + 16384;

        #pragma unroll
        for (int ks = 0; ks < 4; ks++) {
            uint32_t afr[4][4], bfr[2][4];
            const uint32_t chsw = (uint32_t)(((ks * 2 + cq) ^ r7) << 4);
            #pragma unroll
            for (int mt = 0; mt < 4; mt++)
                ldsm4(afr[mt], aB + (uint32_t)((wm + mt * 16 + rA) << 7) + chsw);
            #pragma unroll
            for (int ng = 0; ng < 2; ng++)
                ldsm4(bfr[ng], bB + (uint32_t)((wn + ng * 16 + rA) << 7) + chsw);
            #pragma unroll
            for (int mt = 0; mt < 4; mt++) {
                #pragma unroll
                for (int nt = 0; nt < 4; nt++) {
                    const int ng = nt >> 1, hl = nt & 1;
                    mma16816(acc[mt][nt], afr[mt], bfr[ng][hl], bfr[ng][hl + 2]);
                }
            }
        }
    }

    // epilogue
    const int trow = lane >> 2;
    const int tcol = (lane & 3) * 2;
    #pragma unroll
    for (int mt = 0; mt < 4; mt++) {
        #pragma unroll
        for (int nt = 0; nt < 4; nt++) {
            const int col = n0 + wn + nt * 8 + tcol;
            if (col < Nreal) {
                const float2 b2 = *reinterpret_cast<const float2*>(bias + col);
                const int row0 = m0 + wm + mt * 16 + trow;
                float2 o0, o1;
                o0.x = acc[mt][nt][0] + b2.x;  o0.y = acc[mt][nt][1] + b2.y;
                o1.x = acc[mt][nt][2] + b2.x;  o1.y = acc[mt][nt][3] + b2.y;
                *reinterpret_cast<float2*>(C + (size_t)row0 * Nreal + col)       = o0;
                *reinterpret_cast<float2*>(C + (size_t)(row0 + 8) * Nreal + col) = o1;
            }
        }
    }
}

// ---------------------------------------------------------------------------
// fp32 -> fp16 hi/lo split (elementwise)
// ---------------------------------------------------------------------------
__global__ void split_kernel(const float* __restrict__ in,
                             __half* __restrict__ hi, __half* __restrict__ lo,
                             int n4)
{
    int i = blockIdx.x * blockDim.x + threadIdx.x;
    if (i >= n4) return;
    float4 v = reinterpret_cast<const float4*>(in)[i];
    __half h0 = __float2half_rn(v.x), h1 = __float2half_rn(v.y);
    __half h2 = __float2half_rn(v.z), h3 = __float2half_rn(v.w);
    __half l0 = __float2half_rn(v.x - __half2float(h0));
    __half l1 = __float2half_rn(v.y - __half2float(h1));
    __half l2 = __float2half_rn(v.z - __half2float(h2));
    __half l3 = __float2half_rn(v.w - __half2float(h3));
    reinterpret_cast<__half2*>(hi)[2 * i + 0] = __halves2half2(h0, h1);
    reinterpret_cast<__half2*>(hi)[2 * i + 1] = __halves2half2(h2, h3);
    reinterpret_cast<__half2*>(lo)[2 * i + 0] = __halves2half2(l0, l1);
    reinterpret_cast<__half2*>(lo)[2 * i + 1] = __halves2half2(l2, l3);
}

// ---------------------------------------------------------------------------
// Transpose + split: W [K,N] fp32 -> hi/lo fp16 [Npad,K] (rows >= N zeroed)
// ---------------------------------------------------------------------------
__global__ void tsplit_kernel(const float* __restrict__ W, int K, int N, int Npad,
                              __half* __restrict__ hi, __half* __restrict__ lo)
{
    __shared__ float tile[32][33];
    const int n0 = blockIdx.x * 32;
    const int k0 = blockIdx.y * 32;
    const int tx = threadIdx.x, ty = threadIdx.y;

    #pragma unroll
    for (int r = ty; r < 32; r += 8) {
        int n = n0 + tx, k = k0 + r;
        tile[r][tx] = (n < N) ? W[(size_t)k * N + n] : 0.0f;
    }
    __syncthreads();
    #pragma unroll
    for (int r = ty; r < 32; r += 8) {
        int n = n0 + r, k = k0 + tx;
        float v = tile[tx][r];
        __half h = __float2half_rn(v);
        hi[(size_t)n * K + k] = h;
        lo[(size_t)n * K + k] = __float2half_rn(v - __half2float(h));
    }
}

// ---------------------------------------------------------------------------
// YaRN RoPE in-place on fp32 qkv
// ---------------------------------------------------------------------------
__global__ void rope_kernel(const int* __restrict__ positions,
                            float* __restrict__ qkv)
{
    const int idx = blockIdx.x * blockDim.x + threadIdx.x;
    const int total = T_LEN * (N_HEADS + N_KV) * 32;
    if (idx >= total) return;

    const int d    = idx & 31;
    const int head = (idx >> 5) % (N_HEADS + N_KV);
    const int t    = idx / (32 * (N_HEADS + N_KV));

    const float p = (float)positions[t];
    const float lnB   = logf(150000.0f);
    const float freq  = expf(lnB * ((float)d / 32.0f));
    const float conc  = 0.1f * logf(32.0f) + 1.0f;
    const float twoPi = 6.283185307179586f;
    const float low   = 32.0f * logf(4096.0f / (32.0f * twoPi)) / lnB;
    const float high  = 32.0f * logf(4096.0f / (1.0f  * twoPi)) / lnB;
    float ramp = ((float)d - low) / (high - low);
    ramp = fminf(fmaxf(ramp, 0.0f), 1.0f);
    const float inv_freq = ramp / (32.0f * freq) + (1.0f - ramp) / freq;

    const float ang = p * inv_freq;
    const float c = cosf(ang) * conc;
    const float s = sinf(ang) * conc;

    float* base = qkv + (size_t)t * QKV_COLS + head * HEAD_DIM;
    const float x1 = base[d];
    const float x2 = base[d + 32];
    base[d]      = x1 * c - x2 * s;
    base[d + 32] = x2 * c + x1 * s;
}

// ---------------------------------------------------------------------------
// Smem-blocked sliding-window attention with sink.
// Block = (kv head, 32-query block). 256 threads; warp w owns q-head kv*8+w.
// K/V window rows staged once in smem; out as fp16 hi/lo.
// ---------------------------------------------------------------------------
#define KV_ROWS 160
#define ROWPAD  68
#define ATTN_DSMEM ((2 * KV_ROWS * ROWPAD + 8 * 32 * ROWPAD + 8 * 128) * 4)

__global__ __launch_bounds__(256)
void attn_kernel(const float* __restrict__ qkv, const float* __restrict__ sinks,
                 __half* __restrict__ out_hi, __half* __restrict__ out_lo)
{
    extern __shared__ float sm[];
    float* K_s = sm;                               // [160][68]
    float* V_s = K_s + KV_ROWS * ROWPAD;           // [160][68]
    float* q_s = V_s + KV_ROWS * ROWPAD;           // [8][32][68]
    float* p_s = q_s + 8 * 32 * ROWPAD;            // [8][128]

    const int tid  = threadIdx.x;
    const int warp = tid >> 5;
    const int lane = tid & 31;
    const int i0   = blockIdx.x * 32;
    const int kv   = blockIdx.y;
    const int h    = kv * 8 + warp;

    // stage K/V rows [i0-127 .. i0+31]
    for (int idx = tid; idx < 159 * 64; idx += 256) {
        const int s = idx >> 6, d = idx & 63;
        const int j = i0 - 127 + s;
        float kval = 0.0f, vval = 0.0f;
        if (j >= 0) {
            const float* src = qkv + (size_t)j * QKV_COLS + Q_SIZE + kv * 64 + d;
            kval = src[0];
            vval = src[KV_SIZE];
        }
        K_s[s * ROWPAD + d] = kval;
        V_s[s * ROWPAD + d] = vval;
    }
    // stage this warp's 32 q vectors
    float* qw = q_s + warp * 32 * ROWPAD;
    for (int idx = lane; idx < 32 * 64; idx += 32) {
        const int qq = idx >> 6, d = idx & 63;
        qw[qq * ROWPAD + d] = qkv[(size_t)(i0 + qq) * QKV_COLS + h * 64 + d];
    }
    __syncthreads();

    const float snk = sinks[h];
    float* pw = p_s + warp * 128;

    for (int qq = 0; qq < 32; qq++) {
        const int i = i0 + qq;
        float sc[4] = {0.f, 0.f, 0.f, 0.f};
        const float* qrow = qw + qq * ROWPAD;
        #pragma unroll
        for (int d4 = 0; d4 < 16; d4++) {
            const float4 qv = *reinterpret_cast<const float4*>(qrow + d4 * 4);
            #pragma unroll
            for (int jj = 0; jj < 4; jj++) {
                const float4 kvv = *reinterpret_cast<const float4*>(
                    K_s + (qq + jj * 32 + lane) * ROWPAD + d4 * 4);
                sc[jj] += qv.x * kvv.x + qv.y * kvv.y + qv.z * kvv.z + qv.w * kvv.w;
            }
        }
        float mloc = -3.0e38f;
        #pragma unroll
        for (int jj = 0; jj < 4; jj++) {
            const int j = i - 127 + jj * 32 + lane;
            sc[jj] = (j >= 0) ? sc[jj] * ATT_SCALE : -3.0e38f;
            mloc = fmaxf(mloc, sc[jj]);
        }
        #pragma unroll
        for (int off = 16; off > 0; off >>= 1)
            mloc = fmaxf(mloc, __shfl_xor_sync(0xFFFFFFFFu, mloc, off));
        const float m = fmaxf(mloc, snk);

        float dloc = 0.0f;
        #pragma unroll
        for (int jj = 0; jj < 4; jj++) {
            const float e = expf(sc[jj] - m);
            pw[jj * 32 + lane] = e;
            dloc += e;
        }
        #pragma unroll
        for (int off = 16; off > 0; off >>= 1)
            dloc += __shfl_xor_sync(0xFFFFFFFFu, dloc, off);
        const float inv = 1.0f / (dloc + expf(snk - m));
        __syncwarp();

        float a0 = 0.0f, a1 = 0.0f;
        #pragma unroll 4
        for (int rel = 0; rel < 128; rel++) {
            const float  pj   = pw[rel];
            const float* vrow = V_s + (qq + rel) * ROWPAD;
            a0 += pj * vrow[lane];
            a1 += pj * vrow[lane + 32];
        }
        const float v0 = a0 * inv, v1 = a1 * inv;
        const size_t o = (size_t)i * Q_SIZE + h * 64 + lane;
        const __half h0 = __float2half_rn(v0);
        const __half h1 = __float2half_rn(v1);
        out_hi[o]      = h0;
        out_hi[o + 32] = h1;
        out_lo[o]      = __float2half_rn(v0 - __half2float(h0));
        out_lo[o + 32] = __float2half_rn(v1 - __half2float(h1));
        __syncwarp();
    }
}

// ---------------------------------------------------------------------------
// Launch
// ---------------------------------------------------------------------------
extern "C" void kernel_launch(void* const* d_in, const int* in_sizes, int n_in,
                              void* d_out, int out_size)
{
    const int*   positions = (const int*)  d_in[0];
    const float* hidden    = (const float*)d_in[1];
    const float* W_qkv     = (const float*)d_in[2];
    const float* b_qkv     = (const float*)d_in[3];
    const float* W_o       = (const float*)d_in[4];
    const float* b_o       = (const float*)d_in[5];
    const float* sinks     = (const float*)d_in[6];
    float* out = (float*)d_out;

    float *qkv;
    __half *h_hi, *h_lo, *wq_hi, *wq_lo, *wo_hi, *wo_lo, *a_hi, *a_lo;
    cudaGetSymbolAddress((void**)&qkv,   g_qkv);
    cudaGetSymbolAddress((void**)&h_hi,  g_h_hi);
    cudaGetSymbolAddress((void**)&h_lo,  g_h_lo);
    cudaGetSymbolAddress((void**)&wq_hi, g_wq_hi);
    cudaGetSymbolAddress((void**)&wq_lo, g_wq_lo);
    cudaGetSymbolAddress((void**)&wo_hi, g_wo_hi);
    cudaGetSymbolAddress((void**)&wo_lo, g_wo_lo);
    cudaGetSymbolAddress((void**)&a_hi,  g_a_hi);
    cudaGetSymbolAddress((void**)&a_lo,  g_a_lo);

    static bool attr_done = false;
    if (!attr_done) {
        cudaFuncSetAttribute(hgemm3_kernel,
                             cudaFuncAttributeMaxDynamicSharedMemorySize, GEMM_DSMEM);
        cudaFuncSetAttribute(attn_kernel,
                             cudaFuncAttributeMaxDynamicSharedMemorySize, ATTN_DSMEM);
        attr_done = true;
    }

    // 0a) split hidden -> fp16 hi/lo
    {
        const int n4 = T_LEN * HIDDEN / 4;
        split_kernel<<<(n4 + 255) / 256, 256>>>(hidden, h_hi, h_lo, n4);
    }
    // 0b) transpose + split weights
    {
        dim3 b(32, 8);
        dim3 g1(QKV_COLS / 32, HIDDEN / 32);
        tsplit_kernel<<<g1, b>>>(W_qkv, HIDDEN, QKV_COLS, QKV_COLS, wq_hi, wq_lo);
        dim3 g2(O_NPAD / 32, Q_SIZE / 32);
        tsplit_kernel<<<g2, b>>>(W_o, Q_SIZE, HIDDEN, O_NPAD, wo_hi, wo_lo);
    }
    // 1) QKV projection
    {
        dim3 grid(QKV_COLS / 128, T_LEN / 128);
        hgemm3_kernel<<<grid, 256, GEMM_DSMEM>>>(h_hi, h_lo, wq_hi, wq_lo,
                                                 b_qkv, qkv, QKV_COLS, HIDDEN);
    }
    // 2) RoPE
    {
        const int total = T_LEN * (N_HEADS + N_KV) * 32;
        rope_kernel<<<(total + 255) / 256, 256>>>(positions, qkv);
    }
    // 3) attention
    {
        dim3 grid(T_LEN / 32, N_KV);
        attn_kernel<<<grid, 256, ATTN_DSMEM>>>(qkv, sinks, a_hi, a_lo);
    }
    // 4) O projection
    {
        dim3 grid(O_NPAD / 128, T_LEN / 128);
        hgemm3_kernel<<<grid, 256, GEMM_DSMEM>>>(a_hi, a_lo, wo_hi, wo_lo,
                                                 b_o, out, HIDDEN, Q_SIZE);
    }
}

// round 4
// speedup vs baseline: 3.8576x; 1.5756x over previous
#include <cuda_runtime.h>
#include <cuda_fp16.h>
#include <cstdint>
#include <cmath>

// ---------------------------------------------------------------------------
// GPT-OSS attention block on sm_100 (legacy mma.sync path).
// Round 4: 2-pass hi/lo fp16 GEMMs with fused per-chunk passes (1 barrier /
// 128 MMAs), 4-stage cp.async pipeline; attention with 4-query register
// tiling (KV smem rows shared across 4 queries).
// ---------------------------------------------------------------------------

#define T_LEN      1536
#define HIDDEN     2880
#define N_HEADS    64
#define N_KV       8
#define HEAD_DIM   64
#define WINDOW     128
#define Q_SIZE     4096
#define KV_SIZE    512
#define QKV_COLS   5120
#define O_NPAD     2944
#define ATT_SCALE  0.125f

// ---------------- scratch ---------------------------------------------------
__device__ __align__(256) float  g_qkv   [(size_t)T_LEN * QKV_COLS];
__device__ __align__(256) __half g_h_hi  [(size_t)T_LEN * HIDDEN];
__device__ __align__(256) __half g_wq_hi [(size_t)QKV_COLS * HIDDEN];   // [N,K]
__device__ __align__(256) __half g_wq_lo [(size_t)QKV_COLS * HIDDEN];
__device__ __align__(256) __half g_wo_hi [(size_t)O_NPAD * Q_SIZE];     // [N,K]
__device__ __align__(256) __half g_wo_lo [(size_t)O_NPAD * Q_SIZE];
__device__ __align__(256) __half g_a_hi  [(size_t)T_LEN * Q_SIZE];

// ---------------- helpers ---------------------------------------------------
static __device__ __forceinline__ uint32_t smem_u32(const void* p) {
    uint32_t a;
    asm("{ .reg .u64 t; cvta.to.shared.u64 t, %1; cvt.u32.u64 %0, t; }"
        : "=r"(a) : "l"(p));
    return a;
}

#define CP_ASYNC16(dst, src) \
    asm volatile("cp.async.cg.shared.global [%0], [%1], 16;" :: "r"(dst), "l"(src))
#define CP_COMMIT() asm volatile("cp.async.commit_group;")
#define CP_WAIT2()  asm volatile("cp.async.wait_group 2;")

static __device__ __forceinline__ void ldsm4(uint32_t* r, uint32_t addr) {
    asm volatile("ldmatrix.sync.aligned.m8n8.x4.shared.b16 {%0,%1,%2,%3}, [%4];"
                 : "=r"(r[0]), "=r"(r[1]), "=r"(r[2]), "=r"(r[3]) : "r"(addr));
}

static __device__ __forceinline__ void mma16816(float* d, const uint32_t* a,
                                                uint32_t b0, uint32_t b1) {
    asm volatile("mma.sync.aligned.m16n8k16.row.col.f32.f16.f16.f32 "
                 "{%0,%1,%2,%3}, {%4,%5,%6,%7}, {%8,%9}, {%0,%1,%2,%3};"
                 : "+f"(d[0]), "+f"(d[1]), "+f"(d[2]), "+f"(d[3])
                 : "r"(a[0]), "r"(a[1]), "r"(a[2]), "r"(a[3]), "r"(b0), "r"(b1));
}

// ---------------------------------------------------------------------------
// 2-pass fp16 HMMA GEMM:  C[M,Nreal] = A_hi[M,K] @ (B_hi+B_lo)[Npad,K]^T + bias
// CTA 128x128, K-chunk 64, stage = {Ahi 16K, Bhi 16K, Blo 16K}, 4 stages,
// 256 threads (8 warps of 64x32). One __syncthreads per chunk.
// ---------------------------------------------------------------------------
#define GS           4
#define STAGE_BYTES  49152
#define GEMM_DSMEM   (GS * STAGE_BYTES + 1024)

static __device__ __forceinline__ void load_chunk(
    uint32_t st,
    const __half* __restrict__ Ah, const __half* __restrict__ Bh,
    const __half* __restrict__ Bl,
    int m0, int n0, int kk, int K, int tid)
{
    #pragma unroll
    for (int i = 0; i < 2; i++) {
        int chunk = tid + (i << 8);          // 0..511
        #pragma unroll
        for (int half2x = 0; half2x < 2; half2x++) {
            int ch  = chunk + (half2x << 9);  // 0..1023
            int rw  = ch >> 3;                // row 0..127
            int c16 = ch & 7;                 // 16B chunk in row
            uint32_t off = (uint32_t)(rw << 7) + (uint32_t)(c16 << 4);
            uint32_t sw  = off ^ ((off >> 3) & 0x70);
            const char* sa = (const char*)(Ah + (size_t)(m0 + rw) * K + kk) + (c16 << 4);
            const char* sh = (const char*)(Bh + (size_t)(n0 + rw) * K + kk) + (c16 << 4);
            const char* sl = (const char*)(Bl + (size_t)(n0 + rw) * K + kk) + (c16 << 4);
            CP_ASYNC16(st + sw,         sa);
            CP_ASYNC16(st + 16384 + sw, sh);
            CP_ASYNC16(st + 32768 + sw, sl);
        }
    }
}

__global__ __launch_bounds__(256)
void hgemm2_kernel(const __half* __restrict__ A_hi,
                   const __half* __restrict__ B_hi, const __half* __restrict__ B_lo,
                   const float* __restrict__ bias, float* __restrict__ C,
                   int Nreal, int K)
{
    extern __shared__ char dynsmem[];
    const uint32_t tile0 = (smem_u32(dynsmem) + 1023u) & ~1023u;

    const int tid  = threadIdx.x;
    const int wid  = tid >> 5;
    const int lane = tid & 31;
    const int m0   = blockIdx.y * 128;
    const int n0   = blockIdx.x * 128;
    const int wm   = (wid & 1) * 64;
    const int wn   = (wid >> 1) * 32;

    const int r7 = lane & 7;
    const int q  = lane >> 3;
    const int rA = ((q & 1) << 3) + r7;
    const int cq = q >> 1;

    const int nch = K >> 6;

    float acc[4][4][4];
    #pragma unroll
    for (int a = 0; a < 4; a++)
        #pragma unroll
        for (int b = 0; b < 4; b++)
            #pragma unroll
            for (int c = 0; c < 4; c++) acc[a][b][c] = 0.0f;

    // prologue: chunks 0..GS-2
    #pragma unroll
    for (int c = 0; c < GS - 1; c++) {
        load_chunk(tile0 + c * STAGE_BYTES, A_hi, B_hi, B_lo, m0, n0, c << 6, K, tid);
        CP_COMMIT();
    }

    for (int c = 0; c < nch; c++) {
        CP_WAIT2();
        __syncthreads();

        const int cn = c + GS - 1;
        if (cn < nch)
            load_chunk(tile0 + (cn % GS) * STAGE_BYTES, A_hi, B_hi, B_lo,
                       m0, n0, cn << 6, K, tid);
        CP_COMMIT();

        const uint32_t aB  = tile0 + (c % GS) * STAGE_BYTES;
        const uint32_t bhB = aB + 16384;
        const uint32_t blB = aB + 32768;

        #pragma unroll
        for (int ks = 0; ks < 4; ks++) {
            uint32_t afr[4][4], bfr[2][4];
            const uint32_t chsw = (uint32_t)(((ks * 2 + cq) ^ r7) << 4);
            #pragma unroll
            for (int mt = 0; mt < 4; mt++)
                ldsm4(afr[mt], aB + (uint32_t)((wm + mt * 16 + rA) << 7) + chsw);
            // pass 0: A_hi * B_hi
            #pragma unroll
            for (int ng = 0; ng < 2; ng++)
                ldsm4(bfr[ng], bhB + (uint32_t)((wn + ng * 16 + rA) << 7) + chsw);
            #pragma unroll
            for (int mt = 0; mt < 4; mt++)
                #pragma unroll
                for (int nt = 0; nt < 4; nt++) {
                    const int ng = nt >> 1, hl = nt & 1;
                    mma16816(acc[mt][nt], afr[mt], bfr[ng][hl], bfr[ng][hl + 2]);
                }
            // pass 1: A_hi * B_lo (same accumulators)
            #pragma unroll
            for (int ng = 0; ng < 2; ng++)
                ldsm4(bfr[ng], blB + (uint32_t)((wn + ng * 16 + rA) << 7) + chsw);
            #pragma unroll
            for (int mt = 0; mt < 4; mt++)
                #pragma unroll
                for (int nt = 0; nt < 4; nt++) {
                    const int ng = nt >> 1, hl = nt & 1;
                    mma16816(acc[mt][nt], afr[mt], bfr[ng][hl], bfr[ng][hl + 2]);
                }
        }
    }

    // epilogue
    const int trow = lane >> 2;
    const int tcol = (lane & 3) * 2;
    #pragma unroll
    for (int mt = 0; mt < 4; mt++) {
        #pragma unroll
        for (int nt = 0; nt < 4; nt++) {
            const int col = n0 + wn + nt * 8 + tcol;
            if (col < Nreal) {
                const float2 b2 = *reinterpret_cast<const float2*>(bias + col);
                const int row0 = m0 + wm + mt * 16 + trow;
                float2 o0, o1;
                o0.x = acc[mt][nt][0] + b2.x;  o0.y = acc[mt][nt][1] + b2.y;
                o1.x = acc[mt][nt][2] + b2.x;  o1.y = acc[mt][nt][3] + b2.y;
                *reinterpret_cast<float2*>(C + (size_t)row0 * Nreal + col)       = o0;
                *reinterpret_cast<float2*>(C + (size_t)(row0 + 8) * Nreal + col) = o1;
            }
        }
    }
}

// ---------------------------------------------------------------------------
// fp32 -> fp16 (hi only; activation low bits dropped by design)
// ---------------------------------------------------------------------------
__global__ void split_hi_kernel(const float* __restrict__ in,
                                __half* __restrict__ hi, int n4)
{
    int i = blockIdx.x * blockDim.x + threadIdx.x;
    if (i >= n4) return;
    float4 v = reinterpret_cast<const float4*>(in)[i];
    reinterpret_cast<__half2*>(hi)[2 * i + 0] =
        __halves2half2(__float2half_rn(v.x), __float2half_rn(v.y));
    reinterpret_cast<__half2*>(hi)[2 * i + 1] =
        __halves2half2(__float2half_rn(v.z), __float2half_rn(v.w));
}

// ---------------------------------------------------------------------------
// Transpose + split: W [K,N] fp32 -> hi/lo fp16 [Npad,K]
// ---------------------------------------------------------------------------
__global__ void tsplit_kernel(const float* __restrict__ W, int K, int N, int Npad,
                              __half* __restrict__ hi, __half* __restrict__ lo)
{
    __shared__ float tile[32][33];
    const int n0 = blockIdx.x * 32;
    const int k0 = blockIdx.y * 32;
    const int tx = threadIdx.x, ty = threadIdx.y;

    #pragma unroll
    for (int r = ty; r < 32; r += 8) {
        int n = n0 + tx, k = k0 + r;
        tile[r][tx] = (n < N) ? W[(size_t)k * N + n] : 0.0f;
    }
    __syncthreads();
    #pragma unroll
    for (int r = ty; r < 32; r += 8) {
        int n = n0 + r, k = k0 + tx;
        float v = tile[tx][r];
        __half h = __float2half_rn(v);
        hi[(size_t)n * K + k] = h;
        lo[(size_t)n * K + k] = __float2half_rn(v - __half2float(h));
    }
}

// ---------------------------------------------------------------------------
// YaRN RoPE in-place on fp32 qkv
// ---------------------------------------------------------------------------
__global__ void rope_kernel(const int* __restrict__ positions,
                            float* __restrict__ qkv)
{
    const int idx = blockIdx.x * blockDim.x + threadIdx.x;
    const int total = T_LEN * (N_HEADS + N_KV) * 32;
    if (idx >= total) return;

    const int d    = idx & 31;
    const int head = (idx >> 5) % (N_HEADS + N_KV);
    const int t    = idx / (32 * (N_HEADS + N_KV));

    const float p = (float)positions[t];
    const float lnB   = logf(150000.0f);
    const float freq  = expf(lnB * ((float)d / 32.0f));
    const float conc  = 0.1f * logf(32.0f) + 1.0f;
    const float twoPi = 6.283185307179586f;
    const float low   = 32.0f * logf(4096.0f / (32.0f * twoPi)) / lnB;
    const float high  = 32.0f * logf(4096.0f / (1.0f  * twoPi)) / lnB;
    float ramp = ((float)d - low) / (high - low);
    ramp = fminf(fmaxf(ramp, 0.0f), 1.0f);
    const float inv_freq = ramp / (32.0f * freq) + (1.0f - ramp) / freq;

    const float ang = p * inv_freq;
    const float c = cosf(ang) * conc;
    const float s = sinf(ang) * conc;

    float* base = qkv + (size_t)t * QKV_COLS + head * HEAD_DIM;
    const float x1 = base[d];
    const float x2 = base[d + 32];
    base[d]      = x1 * c - x2 * s;
    base[d + 32] = x2 * c + x1 * s;
}

// ---------------------------------------------------------------------------
// Sliding-window attention, 4-query register tiling.
// Block = (kv head, 32 queries), 256 thr; warp w = head kv*8+w.
// Lane owns absolute KV rows; each K/V smem read feeds 4 queries.
// ---------------------------------------------------------------------------
#define ATT_ROWS 160
#define ATT_PAD  68
#define ATTN_DSMEM ((2 * ATT_ROWS * ATT_PAD + 8 * 4 * ATT_ROWS) * 4)

__global__ __launch_bounds__(256)
void attn_kernel(const float* __restrict__ qkv, const float* __restrict__ sinks,
                 __half* __restrict__ out_hi)
{
    extern __shared__ float sm[];
    float* K_s = sm;                                 // [160][68]
    float* V_s = K_s + ATT_ROWS * ATT_PAD;           // [160][68]
    float* P_s = V_s + ATT_ROWS * ATT_PAD;           // [8][4][160]

    const int tid  = threadIdx.x;
    const int warp = tid >> 5;
    const int lane = tid & 31;
    const int i0   = blockIdx.x * 32;
    const int kv   = blockIdx.y;
    const int h    = kv * 8 + warp;

    // stage K/V rows r=0..158 <-> j = i0-127+r ; row 159 = zero pad
    for (int idx = tid; idx < ATT_ROWS * 64; idx += 256) {
        const int r = idx >> 6, d = idx & 63;
        const int j = i0 - 127 + r;
        float kval = 0.0f, vval = 0.0f;
        if (j >= 0 && r < 159) {
            const float* src = qkv + (size_t)j * QKV_COLS + Q_SIZE + kv * 64 + d;
            kval = src[0];
            vval = src[KV_SIZE];
        }
        K_s[r * ATT_PAD + d] = kval;
        V_s[r * ATT_PAD + d] = vval;
    }
    __syncthreads();

    const float snk = sinks[h];
    float* pw = P_s + warp * (4 * ATT_ROWS);

    for (int g = 0; g < 8; g++) {
        const int qq0 = g * 4;

        float s[5][4];
        #pragma unroll
        for (int jj = 0; jj < 5; jj++)
            #pragma unroll
            for (int qq = 0; qq < 4; qq++) s[jj][qq] = 0.0f;

        const float* qbase = qkv + (size_t)(i0 + qq0) * QKV_COLS + h * 64;
        #pragma unroll
        for (int d4 = 0; d4 < 16; d4++) {
            float4 q4[4];
            #pragma unroll
            for (int qq = 0; qq < 4; qq++)
                q4[qq] = *reinterpret_cast<const float4*>(
                    qbase + (size_t)qq * QKV_COLS + d4 * 4);
            #pragma unroll
            for (int jj = 0; jj < 5; jj++) {
                int r = qq0 + jj * 32 + lane;
                if (r > 159) r = 159;
                const float4 kf = *reinterpret_cast<const float4*>(
                    K_s + r * ATT_PAD + d4 * 4);
                #pragma unroll
                for (int qq = 0; qq < 4; qq++)
                    s[jj][qq] += q4[qq].x * kf.x + q4[qq].y * kf.y +
                                 q4[qq].z * kf.z + q4[qq].w * kf.w;
            }
        }

        float inv[4];
        #pragma unroll
        for (int qq = 0; qq < 4; qq++) {
            float mm = snk;
            #pragma unroll
            for (int jj = 0; jj < 5; jj++) {
                const int R = jj * 32 + lane;
                const bool ok = (R >= qq) && (R <= qq + 127) &&
                                (i0 + qq0 - 127 + R >= 0);
                s[jj][qq] = ok ? s[jj][qq] * ATT_SCALE : -3.0e38f;
                mm = fmaxf(mm, s[jj][qq]);
            }
            #pragma unroll
            for (int off = 16; off > 0; off >>= 1)
                mm = fmaxf(mm, __shfl_xor_sync(0xFFFFFFFFu, mm, off));

            float dsum = 0.0f;
            #pragma unroll
            for (int jj = 0; jj < 5; jj++) {
                const float e = expf(s[jj][qq] - mm);
                pw[qq * ATT_ROWS + jj * 32 + lane] = e;
                dsum += e;
            }
            #pragma unroll
            for (int off = 16; off > 0; off >>= 1)
                dsum += __shfl_xor_sync(0xFFFFFFFFu, dsum, off);
            inv[qq] = 1.0f / (dsum + expf(snk - mm));
        }
        __syncwarp();

        // V phase: rows r = qq0 + R, each feeds 4 queries
        float acc[4][2];
        #pragma unroll
        for (int qq = 0; qq < 4; qq++) { acc[qq][0] = 0.0f; acc[qq][1] = 0.0f; }

        #pragma unroll 4
        for (int R = 0; R < 131; R++) {
            const int r = qq0 + R;
            const float v0 = V_s[r * ATT_PAD + lane];
            const float v1 = V_s[r * ATT_PAD + lane + 32];
            #pragma unroll
            for (int qq = 0; qq < 4; qq++) {
                const float p = pw[qq * ATT_ROWS + R];
                acc[qq][0] += p * v0;
                acc[qq][1] += p * v1;
            }
        }

        #pragma unroll
        for (int qq = 0; qq < 4; qq++) {
            const size_t o = (size_t)(i0 + qq0 + qq) * Q_SIZE + h * 64 + lane;
            out_hi[o]      = __float2half_rn(acc[qq][0] * inv[qq]);
            out_hi[o + 32] = __float2half_rn(acc[qq][1] * inv[qq]);
        }
        __syncwarp();
    }
}

// ---------------------------------------------------------------------------
// Launch
// ---------------------------------------------------------------------------
extern "C" void kernel_launch(void* const* d_in, const int* in_sizes, int n_in,
                              void* d_out, int out_size)
{
    const int*   positions = (const int*)  d_in[0];
    const float* hidden    = (const float*)d_in[1];
    const float* W_qkv     = (const float*)d_in[2];
    const float* b_qkv     = (const float*)d_in[3];
    const float* W_o       = (const float*)d_in[4];
    const float* b_o       = (const float*)d_in[5];
    const float* sinks     = (const float*)d_in[6];
    float* out = (float*)d_out;

    float *qkv;
    __half *h_hi, *wq_hi, *wq_lo, *wo_hi, *wo_lo, *a_hi;
    cudaGetSymbolAddress((void**)&qkv,   g_qkv);
    cudaGetSymbolAddress((void**)&h_hi,  g_h_hi);
    cudaGetSymbolAddress((void**)&wq_hi, g_wq_hi);
    cudaGetSymbolAddress((void**)&wq_lo, g_wq_lo);
    cudaGetSymbolAddress((void**)&wo_hi, g_wo_hi);
    cudaGetSymbolAddress((void**)&wo_lo, g_wo_lo);
    cudaGetSymbolAddress((void**)&a_hi,  g_a_hi);

    static bool attr_done = false;
    if (!attr_done) {
        cudaFuncSetAttribute(hgemm2_kernel,
                             cudaFuncAttributeMaxDynamicSharedMemorySize, GEMM_DSMEM);
        cudaFuncSetAttribute(attn_kernel,
                             cudaFuncAttributeMaxDynamicSharedMemorySize, ATTN_DSMEM);
        attr_done = true;
    }

    // 0a) hidden -> fp16 hi
    {
        const int n4 = T_LEN * HIDDEN / 4;
        split_hi_kernel<<<(n4 + 255) / 256, 256>>>(hidden, h_hi, n4);
    }
    // 0b) transpose + split weights (hi/lo)
    {
        dim3 b(32, 8);
        dim3 g1(QKV_COLS / 32, HIDDEN / 32);
        tsplit_kernel<<<g1, b>>>(W_qkv, HIDDEN, QKV_COLS, QKV_COLS, wq_hi, wq_lo);
        dim3 g2(O_NPAD / 32, Q_SIZE / 32);
        tsplit_kernel<<<g2, b>>>(W_o, Q_SIZE, HIDDEN, O_NPAD, wo_hi, wo_lo);
    }
    // 1) QKV projection
    {
        dim3 grid(QKV_COLS / 128, T_LEN / 128);
        hgemm2_kernel<<<grid, 256, GEMM_DSMEM>>>(h_hi, wq_hi, wq_lo,
                                                 b_qkv, qkv, QKV_COLS, HIDDEN);
    }
    // 2) RoPE
    {
        const int total = T_LEN * (N_HEADS + N_KV) * 32;
        rope_kernel<<<(total + 255) / 256, 256>>>(positions, qkv);
    }
    // 3) attention
    {
        dim3 grid(T_LEN / 32, N_KV);
        attn_kernel<<<grid, 256, ATTN_DSMEM>>>(qkv, sinks, a_hi);
    }
    // 4) O projection
    {
        dim3 grid(O_NPAD / 128, T_LEN / 128);
        hgemm2_kernel<<<grid, 256, GEMM_DSMEM>>>(a_hi, wo_hi, wo_lo,
                                                 b_o, out, HIDDEN, Q_SIZE);
    }
}

// round 5
// speedup vs baseline: 4.0028x; 1.0376x over previous
#include <cuda_runtime.h>
#include <cuda_fp16.h>
#include <cstdint>
#include <cmath>

// ---------------------------------------------------------------------------
// GPT-OSS attention block on sm_100 (legacy mma.sync path).
// Round 5: 2 CTAs/SM for the GEMM (GS=2, 99KB smem, 128-reg cap) to fill the
// tensor-pipe idle cycles seen at occ=12.5%. 2-pass hi/lo fp16 GEMMs,
// attention with 4-query register tiling.
// ---------------------------------------------------------------------------

#define T_LEN      1536
#define HIDDEN     2880
#define N_HEADS    64
#define N_KV       8
#define HEAD_DIM   64
#define WINDOW     128
#define Q_SIZE     4096
#define KV_SIZE    512
#define QKV_COLS   5120
#define O_NPAD     2944
#define ATT_SCALE  0.125f

// ---------------- scratch ---------------------------------------------------
__device__ __align__(256) float  g_qkv   [(size_t)T_LEN * QKV_COLS];
__device__ __align__(256) __half g_h_hi  [(size_t)T_LEN * HIDDEN];
__device__ __align__(256) __half g_wq_hi [(size_t)QKV_COLS * HIDDEN];   // [N,K]
__device__ __align__(256) __half g_wq_lo [(size_t)QKV_COLS * HIDDEN];
__device__ __align__(256) __half g_wo_hi [(size_t)O_NPAD * Q_SIZE];     // [N,K]
__device__ __align__(256) __half g_wo_lo [(size_t)O_NPAD * Q_SIZE];
__device__ __align__(256) __half g_a_hi  [(size_t)T_LEN * Q_SIZE];

// ---------------- helpers ---------------------------------------------------
static __device__ __forceinline__ uint32_t smem_u32(const void* p) {
    uint32_t a;
    asm("{ .reg .u64 t; cvta.to.shared.u64 t, %1; cvt.u32.u64 %0, t; }"
        : "=r"(a) : "l"(p));
    return a;
}

#define CP_ASYNC16(dst, src) \
    asm volatile("cp.async.cg.shared.global [%0], [%1], 16;" :: "r"(dst), "l"(src))
#define CP_COMMIT() asm volatile("cp.async.commit_group;")
#define CP_WAIT1()  asm volatile("cp.async.wait_group 1;")

static __device__ __forceinline__ void ldsm4(uint32_t* r, uint32_t addr) {
    asm volatile("ldmatrix.sync.aligned.m8n8.x4.shared.b16 {%0,%1,%2,%3}, [%4];"
                 : "=r"(r[0]), "=r"(r[1]), "=r"(r[2]), "=r"(r[3]) : "r"(addr));
}

static __device__ __forceinline__ void mma16816(float* d, const uint32_t* a,
                                                uint32_t b0, uint32_t b1) {
    asm volatile("mma.sync.aligned.m16n8k16.row.col.f32.f16.f16.f32 "
                 "{%0,%1,%2,%3}, {%4,%5,%6,%7}, {%8,%9}, {%0,%1,%2,%3};"
                 : "+f"(d[0]), "+f"(d[1]), "+f"(d[2]), "+f"(d[3])
                 : "r"(a[0]), "r"(a[1]), "r"(a[2]), "r"(a[3]), "r"(b0), "r"(b1));
}

// ---------------------------------------------------------------------------
// 2-pass fp16 HMMA GEMM:  C[M,Nreal] = A_hi[M,K] @ (B_hi+B_lo)[Npad,K]^T + bias
// CTA 128x128, K-chunk 64, stage = {Ahi 16K, Bhi 16K, Blo 16K}, GS=2 stages,
// 256 threads (8 warps of 64x32), 2 CTAs/SM.
// ---------------------------------------------------------------------------
#define GS           2
#define STAGE_BYTES  49152
#define GEMM_DSMEM   (GS * STAGE_BYTES + 1024)     // 99,328 B -> 2 CTAs/SM

static __device__ __forceinline__ void load_chunk(
    uint32_t st,
    const __half* __restrict__ Ah, const __half* __restrict__ Bh,
    const __half* __restrict__ Bl,
    int m0, int n0, int kk, int K, int tid)
{
    #pragma unroll
    for (int i = 0; i < 4; i++) {
        int ch  = tid + (i << 8);            // 0..1023
        int rw  = ch >> 3;                   // row 0..127
        int c16 = ch & 7;                    // 16B chunk in row
        uint32_t off = (uint32_t)(rw << 7) + (uint32_t)(c16 << 4);
        uint32_t sw  = off ^ ((off >> 3) & 0x70);
        const char* sa = (const char*)(Ah + (size_t)(m0 + rw) * K + kk) + (c16 << 4);
        const char* sh = (const char*)(Bh + (size_t)(n0 + rw) * K + kk) + (c16 << 4);
        const char* sl = (const char*)(Bl + (size_t)(n0 + rw) * K + kk) + (c16 << 4);
        CP_ASYNC16(st + sw,         sa);
        CP_ASYNC16(st + 16384 + sw, sh);
        CP_ASYNC16(st + 32768 + sw, sl);
    }
}

__global__ __launch_bounds__(256, 2)
void hgemm2_kernel(const __half* __restrict__ A_hi,
                   const __half* __restrict__ B_hi, const __half* __restrict__ B_lo,
                   const float* __restrict__ bias, float* __restrict__ C,
                   int Nreal, int K)
{
    extern __shared__ char dynsmem[];
    const uint32_t tile0 = (smem_u32(dynsmem) + 1023u) & ~1023u;

    const int tid  = threadIdx.x;
    const int wid  = tid >> 5;
    const int lane = tid & 31;
    const int m0   = blockIdx.y * 128;
    const int n0   = blockIdx.x * 128;
    const int wm   = (wid & 1) * 64;
    const int wn   = (wid >> 1) * 32;

    const int r7 = lane & 7;
    const int q  = lane >> 3;
    const int rA = ((q & 1) << 3) + r7;
    const int cq = q >> 1;

    const int nch = K >> 6;

    float acc[4][4][4];
    #pragma unroll
    for (int a = 0; a < 4; a++)
        #pragma unroll
        for (int b = 0; b < 4; b++)
            #pragma unroll
            for (int c = 0; c < 4; c++) acc[a][b][c] = 0.0f;

    // prologue: chunks 0 and 1
    load_chunk(tile0,               A_hi, B_hi, B_lo, m0, n0, 0,  K, tid);
    CP_COMMIT();
    load_chunk(tile0 + STAGE_BYTES, A_hi, B_hi, B_lo, m0, n0, 64, K, tid);
    CP_COMMIT();

    for (int c = 0; c < nch; c++) {
        CP_WAIT1();                 // chunk c resident (newest group may pend)
        __syncthreads();

        const uint32_t aB  = tile0 + (c & 1) * STAGE_BYTES;
        const uint32_t bhB = aB + 16384;
        const uint32_t blB = aB + 32768;

        #pragma unroll
        for (int ks = 0; ks < 4; ks++) {
            uint32_t afr[4][4], bfr[2][4];
            const uint32_t chsw = (uint32_t)(((ks * 2 + cq) ^ r7) << 4);
            #pragma unroll
            for (int mt = 0; mt < 4; mt++)
                ldsm4(afr[mt], aB + (uint32_t)((wm + mt * 16 + rA) << 7) + chsw);
            // pass 0: A_hi * B_hi
            #pragma unroll
            for (int ng = 0; ng < 2; ng++)
                ldsm4(bfr[ng], bhB + (uint32_t)((wn + ng * 16 + rA) << 7) + chsw);
            #pragma unroll
            for (int mt = 0; mt < 4; mt++)
                #pragma unroll
                for (int nt = 0; nt < 4; nt++) {
                    const int ng = nt >> 1, hl = nt & 1;
                    mma16816(acc[mt][nt], afr[mt], bfr[ng][hl], bfr[ng][hl + 2]);
                }
            // pass 1: A_hi * B_lo (same accumulators)
            #pragma unroll
            for (int ng = 0; ng < 2; ng++)
                ldsm4(bfr[ng], blB + (uint32_t)((wn + ng * 16 + rA) << 7) + chsw);
            #pragma unroll
            for (int mt = 0; mt < 4; mt++)
                #pragma unroll
                for (int nt = 0; nt < 4; nt++) {
                    const int ng = nt >> 1, hl = nt & 1;
                    mma16816(acc[mt][nt], afr[mt], bfr[ng][hl], bfr[ng][hl + 2]);
                }
        }

        // free stage (c&1), then refill it with chunk c+2
        __syncthreads();
        if (c + 2 < nch)
            load_chunk(tile0 + (c & 1) * STAGE_BYTES, A_hi, B_hi, B_lo,
                       m0, n0, (c + 2) << 6, K, tid);
        CP_COMMIT();                // empty group when no load: keeps counts aligned
    }

    // epilogue
    const int trow = lane >> 2;
    const int tcol = (lane & 3) * 2;
    #pragma unroll
    for (int mt = 0; mt < 4; mt++) {
        #pragma unroll
        for (int nt = 0; nt < 4; nt++) {
            const int col = n0 + wn + nt * 8 + tcol;
            if (col < Nreal) {
                const float2 b2 = *reinterpret_cast<const float2*>(bias + col);
                const int row0 = m0 + wm + mt * 16 + trow;
                float2 o0, o1;
                o0.x = acc[mt][nt][0] + b2.x;  o0.y = acc[mt][nt][1] + b2.y;
                o1.x = acc[mt][nt][2] + b2.x;  o1.y = acc[mt][nt][3] + b2.y;
                *reinterpret_cast<float2*>(C + (size_t)row0 * Nreal + col)       = o0;
                *reinterpret_cast<float2*>(C + (size_t)(row0 + 8) * Nreal + col) = o1;
            }
        }
    }
}

// ---------------------------------------------------------------------------
// fp32 -> fp16 (hi only)
// ---------------------------------------------------------------------------
__global__ void split_hi_kernel(const float* __restrict__ in,
                                __half* __restrict__ hi, int n4)
{
    int i = blockIdx.x * blockDim.x + threadIdx.x;
    if (i >= n4) return;
    float4 v = reinterpret_cast<const float4*>(in)[i];
    reinterpret_cast<__half2*>(hi)[2 * i + 0] =
        __halves2half2(__float2half_rn(v.x), __float2half_rn(v.y));
    reinterpret_cast<__half2*>(hi)[2 * i + 1] =
        __halves2half2(__float2half_rn(v.z), __float2half_rn(v.w));
}

// ---------------------------------------------------------------------------
// Transpose + split: W [K,N] fp32 -> hi/lo fp16 [Npad,K]
// ---------------------------------------------------------------------------
__global__ void tsplit_kernel(const float* __restrict__ W, int K, int N, int Npad,
                              __half* __restrict__ hi, __half* __restrict__ lo)
{
    __shared__ float tile[32][33];
    const int n0 = blockIdx.x * 32;
    const int k0 = blockIdx.y * 32;
    const int tx = threadIdx.x, ty = threadIdx.y;

    #pragma unroll
    for (int r = ty; r < 32; r += 8) {
        int n = n0 + tx, k = k0 + r;
        tile[r][tx] = (n < N) ? W[(size_t)k * N + n] : 0.0f;
    }
    __syncthreads();
    #pragma unroll
    for (int r = ty; r < 32; r += 8) {
        int n = n0 + r, k = k0 + tx;
        float v = tile[tx][r];
        __half h = __float2half_rn(v);
        hi[(size_t)n * K + k] = h;
        lo[(size_t)n * K + k] = __float2half_rn(v - __half2float(h));
    }
}

// ---------------------------------------------------------------------------
// YaRN RoPE in-place on fp32 qkv
// ---------------------------------------------------------------------------
__global__ void rope_kernel(const int* __restrict__ positions,
                            float* __restrict__ qkv)
{
    const int idx = blockIdx.x * blockDim.x + threadIdx.x;
    const int total = T_LEN * (N_HEADS + N_KV) * 32;
    if (idx >= total) return;

    const int d    = idx & 31;
    const int head = (idx >> 5) % (N_HEADS + N_KV);
    const int t    = idx / (32 * (N_HEADS + N_KV));

    const float p = (float)positions[t];
    const float lnB   = logf(150000.0f);
    const float freq  = expf(lnB * ((float)d / 32.0f));
    const float conc  = 0.1f * logf(32.0f) + 1.0f;
    const float twoPi = 6.283185307179586f;
    const float low   = 32.0f * logf(4096.0f / (32.0f * twoPi)) / lnB;
    const float high  = 32.0f * logf(4096.0f / (1.0f  * twoPi)) / lnB;
    float ramp = ((float)d - low) / (high - low);
    ramp = fminf(fmaxf(ramp, 0.0f), 1.0f);
    const float inv_freq = ramp / (32.0f * freq) + (1.0f - ramp) / freq;

    const float ang = p * inv_freq;
    const float c = cosf(ang) * conc;
    const float s = sinf(ang) * conc;

    float* base = qkv + (size_t)t * QKV_COLS + head * HEAD_DIM;
    const float x1 = base[d];
    const float x2 = base[d + 32];
    base[d]      = x1 * c - x2 * s;
    base[d + 32] = x2 * c + x1 * s;
}

// ---------------------------------------------------------------------------
// Sliding-window attention, 4-query register tiling.
// ---------------------------------------------------------------------------
#define ATT_ROWS 160
#define ATT_PAD  68
#define ATTN_DSMEM ((2 * ATT_ROWS * ATT_PAD + 8 * 4 * ATT_ROWS) * 4)

__global__ __launch_bounds__(256)
void attn_kernel(const float* __restrict__ qkv, const float* __restrict__ sinks,
                 __half* __restrict__ out_hi)
{
    extern __shared__ float sm[];
    float* K_s = sm;                                 // [160][68]
    float* V_s = K_s + ATT_ROWS * ATT_PAD;           // [160][68]
    float* P_s = V_s + ATT_ROWS * ATT_PAD;           // [8][4][160]

    const int tid  = threadIdx.x;
    const int warp = tid >> 5;
    const int lane = tid & 31;
    const int i0   = blockIdx.x * 32;
    const int kv   = blockIdx.y;
    const int h    = kv * 8 + warp;

    for (int idx = tid; idx < ATT_ROWS * 64; idx += 256) {
        const int r = idx >> 6, d = idx & 63;
        const int j = i0 - 127 + r;
        float kval = 0.0f, vval = 0.0f;
        if (j >= 0 && r < 159) {
            const float* src = qkv + (size_t)j * QKV_COLS + Q_SIZE + kv * 64 + d;
            kval = src[0];
            vval = src[KV_SIZE];
        }
        K_s[r * ATT_PAD + d] = kval;
        V_s[r * ATT_PAD + d] = vval;
    }
    __syncthreads();

    const float snk = sinks[h];
    float* pw = P_s + warp * (4 * ATT_ROWS);

    for (int g = 0; g < 8; g++) {
        const int qq0 = g * 4;

        float s[5][4];
        #pragma unroll
        for (int jj = 0; jj < 5; jj++)
            #pragma unroll
            for (int qq = 0; qq < 4; qq++) s[jj][qq] = 0.0f;

        const float* qbase = qkv + (size_t)(i0 + qq0) * QKV_COLS + h * 64;
        #pragma unroll
        for (int d4 = 0; d4 < 16; d4++) {
            float4 q4[4];
            #pragma unroll
            for (int qq = 0; qq < 4; qq++)
                q4[qq] = *reinterpret_cast<const float4*>(
                    qbase + (size_t)qq * QKV_COLS + d4 * 4);
            #pragma unroll
            for (int jj = 0; jj < 5; jj++) {
                int r = qq0 + jj * 32 + lane;
                if (r > 159) r = 159;
                const float4 kf = *reinterpret_cast<const float4*>(
                    K_s + r * ATT_PAD + d4 * 4);
                #pragma unroll
                for (int qq = 0; qq < 4; qq++)
                    s[jj][qq] += q4[qq].x * kf.x + q4[qq].y * kf.y +
                                 q4[qq].z * kf.z + q4[qq].w * kf.w;
            }
        }

        float inv[4];
        #pragma unroll
        for (int qq = 0; qq < 4; qq++) {
            float mm = snk;
            #pragma unroll
            for (int jj = 0; jj < 5; jj++) {
                const int R = jj * 32 + lane;
                const bool ok = (R >= qq) && (R <= qq + 127) &&
                                (i0 + qq0 - 127 + R >= 0);
                s[jj][qq] = ok ? s[jj][qq] * ATT_SCALE : -3.0e38f;
                mm = fmaxf(mm, s[jj][qq]);
            }
            #pragma unroll
            for (int off = 16; off > 0; off >>= 1)
                mm = fmaxf(mm, __shfl_xor_sync(0xFFFFFFFFu, mm, off));

            float dsum = 0.0f;
            #pragma unroll
            for (int jj = 0; jj < 5; jj++) {
                const float e = expf(s[jj][qq] - mm);
                pw[qq * ATT_ROWS + jj * 32 + lane] = e;
                dsum += e;
            }
            #pragma unroll
            for (int off = 16; off > 0; off >>= 1)
                dsum += __shfl_xor_sync(0xFFFFFFFFu, dsum, off);
            inv[qq] = 1.0f / (dsum + expf(snk - mm));
        }
        __syncwarp();

        float acc[4][2];
        #pragma unroll
        for (int qq = 0; qq < 4; qq++) { acc[qq][0] = 0.0f; acc[qq][1] = 0.0f; }

        #pragma unroll 4
        for (int R = 0; R < 131; R++) {
            const int r = qq0 + R;
            const float v0 = V_s[r * ATT_PAD + lane];
            const float v1 = V_s[r * ATT_PAD + lane + 32];
            #pragma unroll
            for (int qq = 0; qq < 4; qq++) {
                const float p = pw[qq * ATT_ROWS + R];
                acc[qq][0] += p * v0;
                acc[qq][1] += p * v1;
            }
        }

        #pragma unroll
        for (int qq = 0; qq < 4; qq++) {
            const size_t o = (size_t)(i0 + qq0 + qq) * Q_SIZE + h * 64 + lane;
            out_hi[o]      = __float2half_rn(acc[qq][0] * inv[qq]);
            out_hi[o + 32] = __float2half_rn(acc[qq][1] * inv[qq]);
        }
        __syncwarp();
    }
}

// ---------------------------------------------------------------------------
// Launch
// ---------------------------------------------------------------------------
extern "C" void kernel_launch(void* const* d_in, const int* in_sizes, int n_in,
                              void* d_out, int out_size)
{
    const int*   positions = (const int*)  d_in[0];
    const float* hidden    = (const float*)d_in[1];
    const float* W_qkv     = (const float*)d_in[2];
    const float* b_qkv     = (const float*)d_in[3];
    const float* W_o       = (const float*)d_in[4];
    const float* b_o       = (const float*)d_in[5];
    const float* sinks     = (const float*)d_in[6];
    float* out = (float*)d_out;

    float *qkv;
    __half *h_hi, *wq_hi, *wq_lo, *wo_hi, *wo_lo, *a_hi;
    cudaGetSymbolAddress((void**)&qkv,   g_qkv);
    cudaGetSymbolAddress((void**)&h_hi,  g_h_hi);
    cudaGetSymbolAddress((void**)&wq_hi, g_wq_hi);
    cudaGetSymbolAddress((void**)&wq_lo, g_wq_lo);
    cudaGetSymbolAddress((void**)&wo_hi, g_wo_hi);
    cudaGetSymbolAddress((void**)&wo_lo, g_wo_lo);
    cudaGetSymbolAddress((void**)&a_hi,  g_a_hi);

    static bool attr_done = false;
    if (!attr_done) {
        cudaFuncSetAttribute(hgemm2_kernel,
                             cudaFuncAttributeMaxDynamicSharedMemorySize, GEMM_DSMEM);
        cudaFuncSetAttribute(attn_kernel,
                             cudaFuncAttributeMaxDynamicSharedMemorySize, ATTN_DSMEM);
        attr_done = true;
    }

    // 0a) hidden -> fp16 hi
    {
        const int n4 = T_LEN * HIDDEN / 4;
        split_hi_kernel<<<(n4 + 255) / 256, 256>>>(hidden, h_hi, n4);
    }
    // 0b) transpose + split weights (hi/lo)
    {
        dim3 b(32, 8);
        dim3 g1(QKV_COLS / 32, HIDDEN / 32);
        tsplit_kernel<<<g1, b>>>(W_qkv, HIDDEN, QKV_COLS, QKV_COLS, wq_hi, wq_lo);
        dim3 g2(O_NPAD / 32, Q_SIZE / 32);
        tsplit_kernel<<<g2, b>>>(W_o, Q_SIZE, HIDDEN, O_NPAD, wo_hi, wo_lo);
    }
    // 1) QKV projection
    {
        dim3 grid(QKV_COLS / 128, T_LEN / 128);
        hgemm2_kernel<<<grid, 256, GEMM_DSMEM>>>(h_hi, wq_hi, wq_lo,
                                                 b_qkv, qkv, QKV_COLS, HIDDEN);
    }
    // 2) RoPE
    {
        const int total = T_LEN * (N_HEADS + N_KV) * 32;
        rope_kernel<<<(total + 255) / 256, 256>>>(positions, qkv);
    }
    // 3) attention
    {
        dim3 grid(T_LEN / 32, N_KV);
        attn_kernel<<<grid, 256, ATTN_DSMEM>>>(qkv, sinks, a_hi);
    }
    // 4) O projection
    {
        dim3 grid(O_NPAD / 128, T_LEN / 128);
        hgemm2_kernel<<<grid, 256, GEMM_DSMEM>>>(a_hi, wo_hi, wo_lo,
                                                 b_o, out, HIDDEN, Q_SIZE);
    }
}